// round 15
// baseline (speedup 1.0000x reference)
#include <cuda_runtime.h>
#include <cuda_bf16.h>
#include <cuda_fp16.h>
#include <cstdint>

#define N_NODES 50000
#define NFEAT   256
#define NHID    128
#define LATENT  64
#define MAX_E   800000

// ---------------- scratch (no allocations allowed) ----------------
__device__ __half g_hpre[(size_t)N_NODES * NHID];  // x@W1 (layer-1 messages, fp16)
__device__ __half g_h   [(size_t)N_NODES * NHID];  // relu(agg1 + b1) (fp16, GEMM2 A operand)
__device__ __half g_hz  [(size_t)N_NODES * NHID];  // h@[Wmu|Wlv] (layer-2 messages, fp16)
__device__ float  g_wcat[NHID * NHID];             // [Wmu | Wlv] packed 128x128
__device__ int    g_cnt [53248];                   // in-degree histogram (padded for int4 scan)
__device__ int    g_rowptr[N_NODES + 1];           // CSR row offsets (by dst)
__device__ int    g_rank[MAX_E];                   // within-bucket rank per edge
__device__ int2   g_ep  [MAX_E];                   // (src, weight-bits) sorted by dst

// ---------------- small utility kernels ----------------
__global__ void zero_int(int* p, int n) {
    int i = blockIdx.x * blockDim.x + threadIdx.x;
    if (i < n) p[i] = 0;
}

__global__ void pack_wcat(const float* __restrict__ Wmu, const float* __restrict__ Wlv,
                          float* __restrict__ Wcat) {
    int i = blockIdx.x * blockDim.x + threadIdx.x;
    if (i >= NHID * NHID) return;
    int k = i >> 7, n = i & 127;
    Wcat[i] = (n < LATENT) ? Wmu[k * LATENT + n] : Wlv[k * LATENT + (n - LATENT)];
}

// ---------------- CSR build ----------------
__global__ void hist_kernel(const int* __restrict__ dst, int* __restrict__ cnt,
                            int* __restrict__ rank, int E) {
    int e = blockIdx.x * blockDim.x + threadIdx.x;
    if (e < E) rank[e] = atomicAdd(&cnt[dst[e]], 1);
}

// single-block scan, int4-vectorized two-pass read
__global__ void scan_kernel(const int* __restrict__ cnt, int* __restrict__ rowptr, int E) {
    __shared__ int sums[1024];
    const int tid = threadIdx.x;
    const int4* c4 = (const int4*)cnt;
    const int b4 = tid * 13;                      // 13 int4 = 52 nodes per thread

    int s = 0;
    #pragma unroll
    for (int i = 0; i < 13; i++) {
        int4 v = c4[b4 + i];
        s += v.x + v.y + v.z + v.w;
    }
    sums[tid] = s;
    __syncthreads();
    #pragma unroll
    for (int d = 1; d < 1024; d <<= 1) {          // Hillis-Steele inclusive
        int add = (tid >= d) ? sums[tid - d] : 0;
        __syncthreads();
        sums[tid] += add;
        __syncthreads();
    }
    int off = sums[tid] - s;                       // exclusive offset
    #pragma unroll
    for (int i = 0; i < 13; i++) {
        int4 v = c4[b4 + i];
        int n = (b4 + i) * 4;
        if (n + 0 < N_NODES) { rowptr[n + 0] = off; off += v.x; }
        if (n + 1 < N_NODES) { rowptr[n + 1] = off; off += v.y; }
        if (n + 2 < N_NODES) { rowptr[n + 2] = off; off += v.z; }
        if (n + 3 < N_NODES) { rowptr[n + 3] = off; off += v.w; }
    }
    if (tid == 0) rowptr[N_NODES] = E;
}

// atomic-free bucket fill using precomputed ranks
__global__ void fill_kernel(const int* __restrict__ src, const int* __restrict__ dst,
                            const float* __restrict__ ew, const int* __restrict__ rank,
                            const int* __restrict__ rowptr, int2* __restrict__ ep, int E) {
    int e = blockIdx.x * blockDim.x + threadIdx.x;
    if (e < E) {
        int p = __ldg(&rowptr[dst[e]]) + rank[e];
        ep[p] = make_int2(src[e], __float_as_int(ew[e]));
    }
}

// ---------------- CSR gather, TWO warps per node ----------------
// Row-load shape preserved (32 lanes x uint2 = full 256B fp16 row, R9-proven).
// The EDGE LIST of each node is split between warp-pair members (even/odd,
// stride 2, unroll-4); partials combine via smem. Block = 8 warps = 4 nodes;
// grid 12500 x 256 covers exactly 50000 nodes (no idle warps, uniform sync).
// MODE 0: h[node,:] = relu(acc + b0) stored as fp16
// MODE 1: out[:N*64] = acc[:64]+b0 (mu); out[N*64:] = acc[64:]+b1v (logvar), fp32
template<int MODE>
__global__ __launch_bounds__(256) void gather_csr2(
    const __half* __restrict__ H, const int2* __restrict__ ep,
    const int* __restrict__ rowptr,
    const float* __restrict__ b0, const float* __restrict__ b1v,
    void* __restrict__ outv)
{
    __shared__ float4 partial[4][32];

    const int gwarp = (blockIdx.x * blockDim.x + threadIdx.x) >> 5;
    const int node  = gwarp >> 1;
    const int sub   = gwarp & 1;                 // which edge stream of the pair
    const int lane  = threadIdx.x & 31;
    const int pairI = (threadIdx.x >> 5) >> 1;   // 0..3 node slot within block

    const int beg = __ldg(&rowptr[node]);
    const int end = __ldg(&rowptr[node + 1]);
    float4 acc = make_float4(0.f, 0.f, 0.f, 0.f);

    auto fma4 = [&](uint2 v, float w) {
        float2 a = __half22float2(*reinterpret_cast<__half2*>(&v.x));
        float2 b = __half22float2(*reinterpret_cast<__half2*>(&v.y));
        acc.x = fmaf(a.x, w, acc.x); acc.y = fmaf(a.y, w, acc.y);
        acc.z = fmaf(b.x, w, acc.z); acc.w = fmaf(b.y, w, acc.w);
    };

    int j = beg + sub;
    for (; j + 6 < end; j += 8) {                // 4 edges, stride 2
        int2 e0 = __ldg(&ep[j]);
        int2 e1 = __ldg(&ep[j + 2]);
        int2 e2 = __ldg(&ep[j + 4]);
        int2 e3 = __ldg(&ep[j + 6]);
        uint2 v0 = __ldg((const uint2*)(H + (size_t)e0.x * NHID) + lane);
        uint2 v1 = __ldg((const uint2*)(H + (size_t)e1.x * NHID) + lane);
        uint2 v2 = __ldg((const uint2*)(H + (size_t)e2.x * NHID) + lane);
        uint2 v3 = __ldg((const uint2*)(H + (size_t)e3.x * NHID) + lane);
        fma4(v0, __int_as_float(e0.y));
        fma4(v1, __int_as_float(e1.y));
        fma4(v2, __int_as_float(e2.y));
        fma4(v3, __int_as_float(e3.y));
    }
    for (; j < end; j += 2) {
        int2 e = __ldg(&ep[j]);
        uint2 v = __ldg((const uint2*)(H + (size_t)e.x * NHID) + lane);
        fma4(v, __int_as_float(e.y));
    }

    // pair combine: sub-1 publishes, sub-0 reduces and writes out
    if (sub == 1) partial[pairI][lane] = acc;
    __syncthreads();
    if (sub == 1) return;
    {
        float4 p = partial[pairI][lane];
        acc.x += p.x; acc.y += p.y; acc.z += p.z; acc.w += p.w;
    }

    if (MODE == 0) {
        __half* out = (__half*)outv;
        float4 b = __ldg((const float4*)b0 + lane);
        __half2 h0 = __floats2half2_rn(fmaxf(acc.x + b.x, 0.f), fmaxf(acc.y + b.y, 0.f));
        __half2 h1 = __floats2half2_rn(fmaxf(acc.z + b.z, 0.f), fmaxf(acc.w + b.w, 0.f));
        uint2 pack;
        pack.x = *reinterpret_cast<uint32_t*>(&h0);
        pack.y = *reinterpret_cast<uint32_t*>(&h1);
        *((uint2*)(out + (size_t)node * NHID) + lane) = pack;
    } else {
        float* out = (float*)outv;
        if (lane < 16) {
            float4 b = __ldg((const float4*)b0 + lane);
            acc.x += b.x; acc.y += b.y; acc.z += b.z; acc.w += b.w;
            *((float4*)(out + (size_t)node * LATENT) + lane) = acc;
        } else {
            float4 b = __ldg((const float4*)b1v + (lane - 16));
            acc.x += b.x; acc.y += b.y; acc.z += b.z; acc.w += b.w;
            *((float4*)(out + (size_t)N_NODES * LATENT + (size_t)node * LATENT) + (lane - 16)) = acc;
        }
    }
}

// ---------------- helpers ----------------
__device__ __forceinline__ uint32_t f2tf32(float v) {
    uint32_t r;
    asm("cvt.rna.tf32.f32 %0, %1;" : "=r"(r) : "f"(v));
    return r;
}

__device__ __forceinline__ void cpasync16(void* smem_dst, const void* gsrc) {
    uint32_t d = (uint32_t)__cvta_generic_to_shared(smem_dst);
    asm volatile("cp.async.ca.shared.global [%0], [%1], 16;" :: "r"(d), "l"(gsrc));
}

#define MMA_TF32(c, a0, a1, a2, a3, b0, b1)                                   \
    asm volatile("mma.sync.aligned.m16n8k8.row.col.f32.tf32.tf32.f32 "        \
                 "{%0,%1,%2,%3}, {%4,%5,%6,%7}, {%8,%9}, {%0,%1,%2,%3};"      \
                 : "+f"((c)[0]), "+f"((c)[1]), "+f"((c)[2]), "+f"((c)[3])     \
                 : "r"(a0), "r"(a1), "r"(a2), "r"(a3), "r"(b0), "r"(b1))

#define PADA 20    // GEMM1 A row stride (floats) -> frag LDS conflict-free
#define PADB 136   // 8t+g -> conflict-free
#define PADH 24    // GEMM2 fp16 A row stride (halves): 48B row step, distinct banks

// ---------------- GEMM1: tf32 3-pass, fp32 in, fp16 out ----------------
__global__ __launch_bounds__(256) void gemm_tf32(
    const float* __restrict__ A, const float* __restrict__ B, __half* __restrict__ C,
    int M, int K)
{
    __shared__ __align__(16) float As[2][128][PADA];   // raw A, [row][k]
    __shared__ __align__(16) float Bs[2][16][PADB];    // raw B, [k][n]

    const int tid  = threadIdx.x;
    const int wid  = tid >> 5;
    const int lane = tid & 31;
    const int g    = lane >> 2;
    const int t    = lane & 3;
    const int wm   = (wid >> 1) * 32;
    const int wn   = (wid & 1) * 64;
    const int m0   = blockIdx.x * 128;

    float acc[2][8][4] = {};

    auto load_tiles = [&](int s, int k0) {
        #pragma unroll
        for (int it = 0; it < 2; it++) {
            int idx = tid + it * 256;
            int row = idx >> 2;
            int kk  = (idx & 3) << 2;
            int gr  = m0 + row;
            if (gr >= M) gr = M - 1;
            cpasync16(&As[s][row][kk], A + (size_t)gr * K + k0 + kk);
        }
        #pragma unroll
        for (int it = 0; it < 2; it++) {
            int idx  = tid + it * 256;
            int krow = idx >> 5;
            int n4   = (idx & 31) << 2;
            cpasync16(&Bs[s][krow][n4], B + (size_t)(k0 + krow) * 128 + n4);
        }
    };

    const int KT = K >> 4;
    load_tiles(0, 0);
    asm volatile("cp.async.commit_group;");

    for (int kt = 0; kt < KT; kt++) {
        const int p = kt & 1;
        if (kt + 1 < KT) {
            load_tiles(p ^ 1, (kt + 1) << 4);
            asm volatile("cp.async.commit_group;");
            asm volatile("cp.async.wait_group 1;");
        } else {
            asm volatile("cp.async.wait_group 0;");
        }
        __syncthreads();

        #pragma unroll
        for (int ks = 0; ks < 16; ks += 8) {
            uint32_t ah[2][4], al[2][4];
            #pragma unroll
            for (int mt = 0; mt < 2; mt++) {
                int mr = wm + mt * 16 + g;
                float ar[4];
                ar[0] = As[p][mr][ks + t];
                ar[1] = As[p][mr + 8][ks + t];
                ar[2] = As[p][mr][ks + t + 4];
                ar[3] = As[p][mr + 8][ks + t + 4];
                #pragma unroll
                for (int q = 0; q < 4; q++) {
                    ah[mt][q] = f2tf32(ar[q]);
                    al[mt][q] = f2tf32(ar[q] - __uint_as_float(ah[mt][q]));
                }
            }
            #pragma unroll
            for (int nt = 0; nt < 8; nt++) {
                int nc = wn + nt * 8 + g;
                float br0 = Bs[p][ks + t][nc];
                float br1 = Bs[p][ks + t + 4][nc];
                uint32_t bh0 = f2tf32(br0);
                uint32_t bl0 = f2tf32(br0 - __uint_as_float(bh0));
                uint32_t bh1 = f2tf32(br1);
                uint32_t bl1 = f2tf32(br1 - __uint_as_float(bh1));
                #pragma unroll
                for (int mt = 0; mt < 2; mt++) {
                    MMA_TF32(acc[mt][nt], ah[mt][0], ah[mt][1], ah[mt][2], ah[mt][3], bh0, bh1);
                    MMA_TF32(acc[mt][nt], ah[mt][0], ah[mt][1], ah[mt][2], ah[mt][3], bl0, bl1);
                    MMA_TF32(acc[mt][nt], al[mt][0], al[mt][1], al[mt][2], al[mt][3], bh0, bh1);
                }
            }
        }
        __syncthreads();
    }

    #pragma unroll
    for (int mt = 0; mt < 2; mt++) {
        #pragma unroll
        for (int nt = 0; nt < 8; nt++) {
            int row = m0 + wm + mt * 16 + g;
            int col = wn + nt * 8 + 2 * t;
            if (row < M)
                *(__half2*)(C + (size_t)row * 128 + col) =
                    __floats2half2_rn(acc[mt][nt][0], acc[mt][nt][1]);
            if (row + 8 < M)
                *(__half2*)(C + (size_t)(row + 8) * 128 + col) =
                    __floats2half2_rn(acc[mt][nt][2], acc[mt][nt][3]);
        }
    }
}

// ---------------- GEMM2: fp16 A (exact in tf32, NO A-split) -> 2-pass mma ----------------
// C[M,128] = A[M,128](fp16) @ B[128,128](fp32, hi/lo split). fp16 out.
__global__ __launch_bounds__(256) void gemm_h16(
    const __half* __restrict__ A, const float* __restrict__ B, __half* __restrict__ C,
    int M)
{
    __shared__ __align__(16) __half As[2][128][PADH];   // fp16 A, [row][k]
    __shared__ __align__(16) float  Bs[2][16][PADB];

    const int tid  = threadIdx.x;
    const int wid  = tid >> 5;
    const int lane = tid & 31;
    const int g    = lane >> 2;
    const int t    = lane & 3;
    const int wm   = (wid >> 1) * 32;
    const int wn   = (wid & 1) * 64;
    const int m0   = blockIdx.x * 128;

    float acc[2][8][4] = {};

    auto load_tiles = [&](int s, int k0) {
        // A tile: 128 rows x 16 halves (32 B/row) = 256 x 16B chunks, 1 per thread
        {
            int row = tid >> 1;
            int kk  = (tid & 1) << 3;              // 0 or 8 halves
            int gr  = m0 + row;
            if (gr >= M) gr = M - 1;
            cpasync16(&As[s][row][kk], A + (size_t)gr * 128 + k0 + kk);
        }
        #pragma unroll
        for (int it = 0; it < 2; it++) {
            int idx  = tid + it * 256;
            int krow = idx >> 5;
            int n4   = (idx & 31) << 2;
            cpasync16(&Bs[s][krow][n4], B + (size_t)(k0 + krow) * 128 + n4);
        }
    };

    load_tiles(0, 0);
    asm volatile("cp.async.commit_group;");

    for (int kt = 0; kt < 8; kt++) {               // K = 128
        const int p = kt & 1;
        if (kt < 7) {
            load_tiles(p ^ 1, (kt + 1) << 4);
            asm volatile("cp.async.commit_group;");
            asm volatile("cp.async.wait_group 1;");
        } else {
            asm volatile("cp.async.wait_group 0;");
        }
        __syncthreads();

        #pragma unroll
        for (int ks = 0; ks < 16; ks += 8) {
            uint32_t ah[2][4];
            #pragma unroll
            for (int mt = 0; mt < 2; mt++) {
                int mr = wm + mt * 16 + g;
                ah[mt][0] = __float_as_uint(__half2float(As[p][mr][ks + t]));
                ah[mt][1] = __float_as_uint(__half2float(As[p][mr + 8][ks + t]));
                ah[mt][2] = __float_as_uint(__half2float(As[p][mr][ks + t + 4]));
                ah[mt][3] = __float_as_uint(__half2float(As[p][mr + 8][ks + t + 4]));
            }
            #pragma unroll
            for (int nt = 0; nt < 8; nt++) {
                int nc = wn + nt * 8 + g;
                float br0 = Bs[p][ks + t][nc];
                float br1 = Bs[p][ks + t + 4][nc];
                uint32_t bh0 = f2tf32(br0);
                uint32_t bl0 = f2tf32(br0 - __uint_as_float(bh0));
                uint32_t bh1 = f2tf32(br1);
                uint32_t bl1 = f2tf32(br1 - __uint_as_float(bh1));
                #pragma unroll
                for (int mt = 0; mt < 2; mt++) {
                    MMA_TF32(acc[mt][nt], ah[mt][0], ah[mt][1], ah[mt][2], ah[mt][3], bh0, bh1);
                    MMA_TF32(acc[mt][nt], ah[mt][0], ah[mt][1], ah[mt][2], ah[mt][3], bl0, bl1);
                }
            }
        }
        __syncthreads();
    }

    #pragma unroll
    for (int mt = 0; mt < 2; mt++) {
        #pragma unroll
        for (int nt = 0; nt < 8; nt++) {
            int row = m0 + wm + mt * 16 + g;
            int col = wn + nt * 8 + 2 * t;
            if (row < M)
                *(__half2*)(C + (size_t)row * 128 + col) =
                    __floats2half2_rn(acc[mt][nt][0], acc[mt][nt][1]);
            if (row + 8 < M)
                *(__half2*)(C + (size_t)(row + 8) * 128 + col) =
                    __floats2half2_rn(acc[mt][nt][2], acc[mt][nt][3]);
        }
    }
}

// ---------------- launch ----------------
// Side stream + events created lazily on the FIRST (uncaptured) call and
// reused during graph capture. CSR build overlaps GEMM1 via fork/join edges.
extern "C" void kernel_launch(void* const* d_in, const int* in_sizes, int n_in,
                              void* d_out, int out_size) {
    const float* x   = (const float*)d_in[0];
    const int*   src = (const int*)  d_in[1];
    const int*   dst = (const int*)  d_in[2];
    const float* ew  = (const float*)d_in[3];
    const float* W1  = (const float*)d_in[4];
    const float* b1  = (const float*)d_in[5];
    const float* Wmu = (const float*)d_in[6];
    const float* bmu = (const float*)d_in[7];
    const float* Wlv = (const float*)d_in[8];
    const float* blv = (const float*)d_in[9];
    float* out = (float*)d_out;
    const int E = in_sizes[1];

    __half *hpre, *h, *hz;
    float *wcat;
    int *cnt, *rowptr, *rank;
    int2 *ep;
    cudaGetSymbolAddress((void**)&hpre,   g_hpre);
    cudaGetSymbolAddress((void**)&h,      g_h);
    cudaGetSymbolAddress((void**)&hz,     g_hz);
    cudaGetSymbolAddress((void**)&wcat,   g_wcat);
    cudaGetSymbolAddress((void**)&cnt,    g_cnt);
    cudaGetSymbolAddress((void**)&rowptr, g_rowptr);
    cudaGetSymbolAddress((void**)&rank,   g_rank);
    cudaGetSymbolAddress((void**)&ep,     g_ep);

    static cudaStream_t s2 = [] {
        cudaStream_t s; cudaStreamCreateWithFlags(&s, cudaStreamNonBlocking); return s;
    }();
    static cudaEvent_t evFork = [] {
        cudaEvent_t e; cudaEventCreateWithFlags(&e, cudaEventDisableTiming); return e;
    }();
    static cudaEvent_t evJoin = [] {
        cudaEvent_t e; cudaEventCreateWithFlags(&e, cudaEventDisableTiming); return e;
    }();

    const int gemm_grid    = (N_NODES + 127) / 128;             // 391
    const int edge_grid    = (E + 255) / 256;
    const int gather_grid2 = (N_NODES * 2 * 32) / 256;          // 12500, exact

    // ---- fork: CSR build + weight pack on s2, GEMM1 on main stream ----
    cudaEventRecord(evFork, 0);
    cudaStreamWaitEvent(s2, evFork, 0);

    zero_int   <<<(N_NODES + 255) / 256, 256, 0, s2>>>(cnt, N_NODES);
    hist_kernel<<<edge_grid, 256, 0, s2>>>(dst, cnt, rank, E);
    scan_kernel<<<1, 1024, 0, s2>>>(cnt, rowptr, E);
    fill_kernel<<<edge_grid, 256, 0, s2>>>(src, dst, ew, rank, rowptr, ep, E);
    pack_wcat  <<<64, 256, 0, s2>>>(Wmu, Wlv, wcat);
    cudaEventRecord(evJoin, s2);

    gemm_tf32<<<gemm_grid, 256>>>(x, W1, hpre, N_NODES, NFEAT);   // main stream

    // ---- join ----
    cudaStreamWaitEvent(0, evJoin, 0);

    // Layer 1 aggregation (2 warps/node): h = relu(segsum(hpre[src]*w, dst) + b1)
    gather_csr2<0><<<gather_grid2, 256>>>(hpre, ep, rowptr, b1, nullptr, h);

    // Layer 2 GEMM (fp16 A, 2-pass): hz = h @ [Wmu|Wlv]
    gemm_h16<<<gemm_grid, 256>>>(h, wcat, hz, N_NODES);

    // Layer 2 aggregation (2 warps/node): out = segsum(hz[src]*w, dst) + [bmu;blv]
    gather_csr2<1><<<gather_grid2, 256>>>(hz, ep, rowptr, bmu, blv, out);
}

// round 16
// speedup vs baseline: 1.0711x; 1.0711x over previous
#include <cuda_runtime.h>
#include <cuda_bf16.h>
#include <cuda_fp16.h>
#include <cstdint>

#define N_NODES 50000
#define NFEAT   256
#define NHID    128
#define LATENT  64
#define MAX_E   800000

// ---------------- scratch (no allocations allowed) ----------------
__device__ __half g_hpre[(size_t)N_NODES * NHID];  // x@W1 (layer-1 messages, fp16)
__device__ __half g_h   [(size_t)N_NODES * NHID];  // relu(agg1 + b1) (fp16, GEMM2 A operand)
__device__ __half g_hz  [(size_t)N_NODES * NHID];  // h@[Wmu|Wlv] (layer-2 messages, fp16)
__device__ float  g_wcat[NHID * NHID];             // [Wmu | Wlv] packed 128x128
__device__ int    g_cnt [53248];                   // in-degree histogram (padded for int4 scan)
__device__ int    g_rowptr[N_NODES + 1];           // CSR row offsets (by dst)
__device__ int    g_rank[MAX_E];                   // within-bucket rank per edge
__device__ int2   g_ep  [MAX_E];                   // (src, weight-bits) sorted by dst

// ---------------- small utility kernels ----------------
__global__ void zero_int(int* p, int n) {
    int i = blockIdx.x * blockDim.x + threadIdx.x;
    if (i < n) p[i] = 0;
}

__global__ void pack_wcat(const float* __restrict__ Wmu, const float* __restrict__ Wlv,
                          float* __restrict__ Wcat) {
    int i = blockIdx.x * blockDim.x + threadIdx.x;
    if (i >= NHID * NHID) return;
    int k = i >> 7, n = i & 127;
    Wcat[i] = (n < LATENT) ? Wmu[k * LATENT + n] : Wlv[k * LATENT + (n - LATENT)];
}

// ---------------- CSR build ----------------
__global__ void hist_kernel(const int* __restrict__ dst, int* __restrict__ cnt,
                            int* __restrict__ rank, int E) {
    int e = blockIdx.x * blockDim.x + threadIdx.x;
    if (e < E) rank[e] = atomicAdd(&cnt[dst[e]], 1);
}

// single-block scan, int4-vectorized two-pass read
__global__ void scan_kernel(const int* __restrict__ cnt, int* __restrict__ rowptr, int E) {
    __shared__ int sums[1024];
    const int tid = threadIdx.x;
    const int4* c4 = (const int4*)cnt;
    const int b4 = tid * 13;                      // 13 int4 = 52 nodes per thread

    int s = 0;
    #pragma unroll
    for (int i = 0; i < 13; i++) {
        int4 v = c4[b4 + i];
        s += v.x + v.y + v.z + v.w;
    }
    sums[tid] = s;
    __syncthreads();
    #pragma unroll
    for (int d = 1; d < 1024; d <<= 1) {          // Hillis-Steele inclusive
        int add = (tid >= d) ? sums[tid - d] : 0;
        __syncthreads();
        sums[tid] += add;
        __syncthreads();
    }
    int off = sums[tid] - s;                       // exclusive offset
    #pragma unroll
    for (int i = 0; i < 13; i++) {
        int4 v = c4[b4 + i];
        int n = (b4 + i) * 4;
        if (n + 0 < N_NODES) { rowptr[n + 0] = off; off += v.x; }
        if (n + 1 < N_NODES) { rowptr[n + 1] = off; off += v.y; }
        if (n + 2 < N_NODES) { rowptr[n + 2] = off; off += v.z; }
        if (n + 3 < N_NODES) { rowptr[n + 3] = off; off += v.w; }
    }
    if (tid == 0) rowptr[N_NODES] = E;
}

// atomic-free bucket fill using precomputed ranks
__global__ void fill_kernel(const int* __restrict__ src, const int* __restrict__ dst,
                            const float* __restrict__ ew, const int* __restrict__ rank,
                            const int* __restrict__ rowptr, int2* __restrict__ ep, int E) {
    int e = blockIdx.x * blockDim.x + threadIdx.x;
    if (e < E) {
        int p = __ldg(&rowptr[dst[e]]) + rank[e];
        ep[p] = make_int2(src[e], __float_as_int(ew[e]));
    }
}

// ---------------- CSR gather (fp16 messages): one warp per node, unroll-8 ----------------
// R13-proven shape (32 lanes x uint2 = full 256B row, warp-independent),
// edge loop deepened to 8-wide MLP to halve serial L2-latency batches.
// MODE 0: h[node,:] = relu(acc + b0) stored as fp16
// MODE 1: out[:N*64] = acc[:64]+b0 (mu); out[N*64:] = acc[64:]+b1v (logvar), fp32
template<int MODE>
__global__ __launch_bounds__(256) void gather_csr(
    const __half* __restrict__ H, const int2* __restrict__ ep,
    const int* __restrict__ rowptr,
    const float* __restrict__ b0, const float* __restrict__ b1v,
    void* __restrict__ outv)
{
    const int node = (blockIdx.x * blockDim.x + threadIdx.x) >> 5;
    const int lane = threadIdx.x & 31;
    if (node >= N_NODES) return;
    const int beg = __ldg(&rowptr[node]);
    const int end = __ldg(&rowptr[node + 1]);
    float4 acc = make_float4(0.f, 0.f, 0.f, 0.f);

    auto fma4 = [&](uint2 v, float w) {
        float2 a = __half22float2(*reinterpret_cast<__half2*>(&v.x));
        float2 b = __half22float2(*reinterpret_cast<__half2*>(&v.y));
        acc.x = fmaf(a.x, w, acc.x); acc.y = fmaf(a.y, w, acc.y);
        acc.z = fmaf(b.x, w, acc.z); acc.w = fmaf(b.y, w, acc.w);
    };

    int j = beg;
    for (; j + 8 <= end; j += 8) {                // 8 edges in flight
        int2 e0 = __ldg(&ep[j]);
        int2 e1 = __ldg(&ep[j + 1]);
        int2 e2 = __ldg(&ep[j + 2]);
        int2 e3 = __ldg(&ep[j + 3]);
        int2 e4 = __ldg(&ep[j + 4]);
        int2 e5 = __ldg(&ep[j + 5]);
        int2 e6 = __ldg(&ep[j + 6]);
        int2 e7 = __ldg(&ep[j + 7]);
        uint2 v0 = __ldg((const uint2*)(H + (size_t)e0.x * NHID) + lane);
        uint2 v1 = __ldg((const uint2*)(H + (size_t)e1.x * NHID) + lane);
        uint2 v2 = __ldg((const uint2*)(H + (size_t)e2.x * NHID) + lane);
        uint2 v3 = __ldg((const uint2*)(H + (size_t)e3.x * NHID) + lane);
        uint2 v4 = __ldg((const uint2*)(H + (size_t)e4.x * NHID) + lane);
        uint2 v5 = __ldg((const uint2*)(H + (size_t)e5.x * NHID) + lane);
        uint2 v6 = __ldg((const uint2*)(H + (size_t)e6.x * NHID) + lane);
        uint2 v7 = __ldg((const uint2*)(H + (size_t)e7.x * NHID) + lane);
        fma4(v0, __int_as_float(e0.y));
        fma4(v1, __int_as_float(e1.y));
        fma4(v2, __int_as_float(e2.y));
        fma4(v3, __int_as_float(e3.y));
        fma4(v4, __int_as_float(e4.y));
        fma4(v5, __int_as_float(e5.y));
        fma4(v6, __int_as_float(e6.y));
        fma4(v7, __int_as_float(e7.y));
    }
    for (; j + 4 <= end; j += 4) {
        int2 e0 = __ldg(&ep[j]);
        int2 e1 = __ldg(&ep[j + 1]);
        int2 e2 = __ldg(&ep[j + 2]);
        int2 e3 = __ldg(&ep[j + 3]);
        uint2 v0 = __ldg((const uint2*)(H + (size_t)e0.x * NHID) + lane);
        uint2 v1 = __ldg((const uint2*)(H + (size_t)e1.x * NHID) + lane);
        uint2 v2 = __ldg((const uint2*)(H + (size_t)e2.x * NHID) + lane);
        uint2 v3 = __ldg((const uint2*)(H + (size_t)e3.x * NHID) + lane);
        fma4(v0, __int_as_float(e0.y));
        fma4(v1, __int_as_float(e1.y));
        fma4(v2, __int_as_float(e2.y));
        fma4(v3, __int_as_float(e3.y));
    }
    for (; j < end; j++) {
        int2 p = __ldg(&ep[j]);
        uint2 v = __ldg((const uint2*)(H + (size_t)p.x * NHID) + lane);
        fma4(v, __int_as_float(p.y));
    }

    if (MODE == 0) {
        __half* out = (__half*)outv;
        float4 b = __ldg((const float4*)b0 + lane);
        __half2 h0 = __floats2half2_rn(fmaxf(acc.x + b.x, 0.f), fmaxf(acc.y + b.y, 0.f));
        __half2 h1 = __floats2half2_rn(fmaxf(acc.z + b.z, 0.f), fmaxf(acc.w + b.w, 0.f));
        uint2 pack;
        pack.x = *reinterpret_cast<uint32_t*>(&h0);
        pack.y = *reinterpret_cast<uint32_t*>(&h1);
        *((uint2*)(out + (size_t)node * NHID) + lane) = pack;
    } else {
        float* out = (float*)outv;
        if (lane < 16) {
            float4 b = __ldg((const float4*)b0 + lane);
            acc.x += b.x; acc.y += b.y; acc.z += b.z; acc.w += b.w;
            *((float4*)(out + (size_t)node * LATENT) + lane) = acc;
        } else {
            float4 b = __ldg((const float4*)b1v + (lane - 16));
            acc.x += b.x; acc.y += b.y; acc.z += b.z; acc.w += b.w;
            *((float4*)(out + (size_t)N_NODES * LATENT + (size_t)node * LATENT) + (lane - 16)) = acc;
        }
    }
}

// ---------------- helpers ----------------
__device__ __forceinline__ uint32_t f2tf32(float v) {
    uint32_t r;
    asm("cvt.rna.tf32.f32 %0, %1;" : "=r"(r) : "f"(v));
    return r;
}

__device__ __forceinline__ void cpasync16(void* smem_dst, const void* gsrc) {
    uint32_t d = (uint32_t)__cvta_generic_to_shared(smem_dst);
    asm volatile("cp.async.ca.shared.global [%0], [%1], 16;" :: "r"(d), "l"(gsrc));
}

#define MMA_TF32(c, a0, a1, a2, a3, b0, b1)                                   \
    asm volatile("mma.sync.aligned.m16n8k8.row.col.f32.tf32.tf32.f32 "        \
                 "{%0,%1,%2,%3}, {%4,%5,%6,%7}, {%8,%9}, {%0,%1,%2,%3};"      \
                 : "+f"((c)[0]), "+f"((c)[1]), "+f"((c)[2]), "+f"((c)[3])     \
                 : "r"(a0), "r"(a1), "r"(a2), "r"(a3), "r"(b0), "r"(b1))

#define PADA 20    // GEMM1 A row stride (floats) -> frag LDS conflict-free
#define PADB 136   // 8t+g -> conflict-free
#define PADH 24    // GEMM2 fp16 A row stride (halves): 48B row step, distinct banks

// ---------------- GEMM1: tf32 3-pass, fp32 in, fp16 out ----------------
__global__ __launch_bounds__(256) void gemm_tf32(
    const float* __restrict__ A, const float* __restrict__ B, __half* __restrict__ C,
    int M, int K)
{
    __shared__ __align__(16) float As[2][128][PADA];   // raw A, [row][k]
    __shared__ __align__(16) float Bs[2][16][PADB];    // raw B, [k][n]

    const int tid  = threadIdx.x;
    const int wid  = tid >> 5;
    const int lane = tid & 31;
    const int g    = lane >> 2;
    const int t    = lane & 3;
    const int wm   = (wid >> 1) * 32;
    const int wn   = (wid & 1) * 64;
    const int m0   = blockIdx.x * 128;

    float acc[2][8][4] = {};

    auto load_tiles = [&](int s, int k0) {
        #pragma unroll
        for (int it = 0; it < 2; it++) {
            int idx = tid + it * 256;
            int row = idx >> 2;
            int kk  = (idx & 3) << 2;
            int gr  = m0 + row;
            if (gr >= M) gr = M - 1;
            cpasync16(&As[s][row][kk], A + (size_t)gr * K + k0 + kk);
        }
        #pragma unroll
        for (int it = 0; it < 2; it++) {
            int idx  = tid + it * 256;
            int krow = idx >> 5;
            int n4   = (idx & 31) << 2;
            cpasync16(&Bs[s][krow][n4], B + (size_t)(k0 + krow) * 128 + n4);
        }
    };

    const int KT = K >> 4;
    load_tiles(0, 0);
    asm volatile("cp.async.commit_group;");

    for (int kt = 0; kt < KT; kt++) {
        const int p = kt & 1;
        if (kt + 1 < KT) {
            load_tiles(p ^ 1, (kt + 1) << 4);
            asm volatile("cp.async.commit_group;");
            asm volatile("cp.async.wait_group 1;");
        } else {
            asm volatile("cp.async.wait_group 0;");
        }
        __syncthreads();

        #pragma unroll
        for (int ks = 0; ks < 16; ks += 8) {
            uint32_t ah[2][4], al[2][4];
            #pragma unroll
            for (int mt = 0; mt < 2; mt++) {
                int mr = wm + mt * 16 + g;
                float ar[4];
                ar[0] = As[p][mr][ks + t];
                ar[1] = As[p][mr + 8][ks + t];
                ar[2] = As[p][mr][ks + t + 4];
                ar[3] = As[p][mr + 8][ks + t + 4];
                #pragma unroll
                for (int q = 0; q < 4; q++) {
                    ah[mt][q] = f2tf32(ar[q]);
                    al[mt][q] = f2tf32(ar[q] - __uint_as_float(ah[mt][q]));
                }
            }
            #pragma unroll
            for (int nt = 0; nt < 8; nt++) {
                int nc = wn + nt * 8 + g;
                float br0 = Bs[p][ks + t][nc];
                float br1 = Bs[p][ks + t + 4][nc];
                uint32_t bh0 = f2tf32(br0);
                uint32_t bl0 = f2tf32(br0 - __uint_as_float(bh0));
                uint32_t bh1 = f2tf32(br1);
                uint32_t bl1 = f2tf32(br1 - __uint_as_float(bh1));
                #pragma unroll
                for (int mt = 0; mt < 2; mt++) {
                    MMA_TF32(acc[mt][nt], ah[mt][0], ah[mt][1], ah[mt][2], ah[mt][3], bh0, bh1);
                    MMA_TF32(acc[mt][nt], ah[mt][0], ah[mt][1], ah[mt][2], ah[mt][3], bl0, bl1);
                    MMA_TF32(acc[mt][nt], al[mt][0], al[mt][1], al[mt][2], al[mt][3], bh0, bh1);
                }
            }
        }
        __syncthreads();
    }

    #pragma unroll
    for (int mt = 0; mt < 2; mt++) {
        #pragma unroll
        for (int nt = 0; nt < 8; nt++) {
            int row = m0 + wm + mt * 16 + g;
            int col = wn + nt * 8 + 2 * t;
            if (row < M)
                *(__half2*)(C + (size_t)row * 128 + col) =
                    __floats2half2_rn(acc[mt][nt][0], acc[mt][nt][1]);
            if (row + 8 < M)
                *(__half2*)(C + (size_t)(row + 8) * 128 + col) =
                    __floats2half2_rn(acc[mt][nt][2], acc[mt][nt][3]);
        }
    }
}

// ---------------- GEMM2: fp16 A (exact in tf32, NO A-split) -> 2-pass mma ----------------
// C[M,128] = A[M,128](fp16) @ B[128,128](fp32, hi/lo split). fp16 out.
__global__ __launch_bounds__(256) void gemm_h16(
    const __half* __restrict__ A, const float* __restrict__ B, __half* __restrict__ C,
    int M)
{
    __shared__ __align__(16) __half As[2][128][PADH];   // fp16 A, [row][k]
    __shared__ __align__(16) float  Bs[2][16][PADB];

    const int tid  = threadIdx.x;
    const int wid  = tid >> 5;
    const int lane = tid & 31;
    const int g    = lane >> 2;
    const int t    = lane & 3;
    const int wm   = (wid >> 1) * 32;
    const int wn   = (wid & 1) * 64;
    const int m0   = blockIdx.x * 128;

    float acc[2][8][4] = {};

    auto load_tiles = [&](int s, int k0) {
        // A tile: 128 rows x 16 halves (32 B/row) = 256 x 16B chunks, 1 per thread
        {
            int row = tid >> 1;
            int kk  = (tid & 1) << 3;              // 0 or 8 halves
            int gr  = m0 + row;
            if (gr >= M) gr = M - 1;
            cpasync16(&As[s][row][kk], A + (size_t)gr * 128 + k0 + kk);
        }
        #pragma unroll
        for (int it = 0; it < 2; it++) {
            int idx  = tid + it * 256;
            int krow = idx >> 5;
            int n4   = (idx & 31) << 2;
            cpasync16(&Bs[s][krow][n4], B + (size_t)(k0 + krow) * 128 + n4);
        }
    };

    load_tiles(0, 0);
    asm volatile("cp.async.commit_group;");

    for (int kt = 0; kt < 8; kt++) {               // K = 128
        const int p = kt & 1;
        if (kt < 7) {
            load_tiles(p ^ 1, (kt + 1) << 4);
            asm volatile("cp.async.commit_group;");
            asm volatile("cp.async.wait_group 1;");
        } else {
            asm volatile("cp.async.wait_group 0;");
        }
        __syncthreads();

        #pragma unroll
        for (int ks = 0; ks < 16; ks += 8) {
            uint32_t ah[2][4];
            #pragma unroll
            for (int mt = 0; mt < 2; mt++) {
                int mr = wm + mt * 16 + g;
                ah[mt][0] = __float_as_uint(__half2float(As[p][mr][ks + t]));
                ah[mt][1] = __float_as_uint(__half2float(As[p][mr + 8][ks + t]));
                ah[mt][2] = __float_as_uint(__half2float(As[p][mr][ks + t + 4]));
                ah[mt][3] = __float_as_uint(__half2float(As[p][mr + 8][ks + t + 4]));
            }
            #pragma unroll
            for (int nt = 0; nt < 8; nt++) {
                int nc = wn + nt * 8 + g;
                float br0 = Bs[p][ks + t][nc];
                float br1 = Bs[p][ks + t + 4][nc];
                uint32_t bh0 = f2tf32(br0);
                uint32_t bl0 = f2tf32(br0 - __uint_as_float(bh0));
                uint32_t bh1 = f2tf32(br1);
                uint32_t bl1 = f2tf32(br1 - __uint_as_float(bh1));
                #pragma unroll
                for (int mt = 0; mt < 2; mt++) {
                    MMA_TF32(acc[mt][nt], ah[mt][0], ah[mt][1], ah[mt][2], ah[mt][3], bh0, bh1);
                    MMA_TF32(acc[mt][nt], ah[mt][0], ah[mt][1], ah[mt][2], ah[mt][3], bl0, bl1);
                }
            }
        }
        __syncthreads();
    }

    #pragma unroll
    for (int mt = 0; mt < 2; mt++) {
        #pragma unroll
        for (int nt = 0; nt < 8; nt++) {
            int row = m0 + wm + mt * 16 + g;
            int col = wn + nt * 8 + 2 * t;
            if (row < M)
                *(__half2*)(C + (size_t)row * 128 + col) =
                    __floats2half2_rn(acc[mt][nt][0], acc[mt][nt][1]);
            if (row + 8 < M)
                *(__half2*)(C + (size_t)(row + 8) * 128 + col) =
                    __floats2half2_rn(acc[mt][nt][2], acc[mt][nt][3]);
        }
    }
}

// ---------------- launch ----------------
// Side stream + events created lazily on the FIRST (uncaptured) call and
// reused during graph capture. CSR build overlaps GEMM1 via fork/join edges.
extern "C" void kernel_launch(void* const* d_in, const int* in_sizes, int n_in,
                              void* d_out, int out_size) {
    const float* x   = (const float*)d_in[0];
    const int*   src = (const int*)  d_in[1];
    const int*   dst = (const int*)  d_in[2];
    const float* ew  = (const float*)d_in[3];
    const float* W1  = (const float*)d_in[4];
    const float* b1  = (const float*)d_in[5];
    const float* Wmu = (const float*)d_in[6];
    const float* bmu = (const float*)d_in[7];
    const float* Wlv = (const float*)d_in[8];
    const float* blv = (const float*)d_in[9];
    float* out = (float*)d_out;
    const int E = in_sizes[1];

    __half *hpre, *h, *hz;
    float *wcat;
    int *cnt, *rowptr, *rank;
    int2 *ep;
    cudaGetSymbolAddress((void**)&hpre,   g_hpre);
    cudaGetSymbolAddress((void**)&h,      g_h);
    cudaGetSymbolAddress((void**)&hz,     g_hz);
    cudaGetSymbolAddress((void**)&wcat,   g_wcat);
    cudaGetSymbolAddress((void**)&cnt,    g_cnt);
    cudaGetSymbolAddress((void**)&rowptr, g_rowptr);
    cudaGetSymbolAddress((void**)&rank,   g_rank);
    cudaGetSymbolAddress((void**)&ep,     g_ep);

    static cudaStream_t s2 = [] {
        cudaStream_t s; cudaStreamCreateWithFlags(&s, cudaStreamNonBlocking); return s;
    }();
    static cudaEvent_t evFork = [] {
        cudaEvent_t e; cudaEventCreateWithFlags(&e, cudaEventDisableTiming); return e;
    }();
    static cudaEvent_t evJoin = [] {
        cudaEvent_t e; cudaEventCreateWithFlags(&e, cudaEventDisableTiming); return e;
    }();

    const int gemm_grid   = (N_NODES + 127) / 128;          // 391
    const int edge_grid   = (E + 255) / 256;
    const int gather_grid = (N_NODES * 32 + 255) / 256;     // warp per node

    // ---- fork: CSR build + weight pack on s2, GEMM1 on main stream ----
    cudaEventRecord(evFork, 0);
    cudaStreamWaitEvent(s2, evFork, 0);

    zero_int   <<<(N_NODES + 255) / 256, 256, 0, s2>>>(cnt, N_NODES);
    hist_kernel<<<edge_grid, 256, 0, s2>>>(dst, cnt, rank, E);
    scan_kernel<<<1, 1024, 0, s2>>>(cnt, rowptr, E);
    fill_kernel<<<edge_grid, 256, 0, s2>>>(src, dst, ew, rank, rowptr, ep, E);
    pack_wcat  <<<64, 256, 0, s2>>>(Wmu, Wlv, wcat);
    cudaEventRecord(evJoin, s2);

    gemm_tf32<<<gemm_grid, 256>>>(x, W1, hpre, N_NODES, NFEAT);   // main stream

    // ---- join ----
    cudaStreamWaitEvent(0, evJoin, 0);

    // Layer 1 aggregation: h = relu(segsum(hpre[src]*w, dst) + b1)  (fp16 out)
    gather_csr<0><<<gather_grid, 256>>>(hpre, ep, rowptr, b1, nullptr, h);

    // Layer 2 GEMM (fp16 A, 2-pass): hz = h @ [Wmu|Wlv]
    gemm_h16<<<gemm_grid, 256>>>(h, wcat, hz, N_NODES);

    // Layer 2 aggregation: out = segsum(hz[src]*w, dst) + [bmu;blv]
    gather_csr<1><<<gather_grid, 256>>>(hz, ep, rowptr, bmu, blv, out);
}